// round 17
// baseline (speedup 1.0000x reference)
#include <cuda_runtime.h>

// Problem constants (fixed by reference_code)
#define Bc 2
#define Nc 65536
#define Hc 128
#define Wc 128
#define HWc 16384
#define Gsplit 32              // split-K factor over gaussians
#define KN (Nc / Gsplit)       // 2048 gaussians per block range
#define KC 32                  // chunk of gaussians staged in smem
#define NTX 8
#define NTILE 64               // tiles per camera (8x8 of 16x16)
#define TDIMX 16
#define TDIMY 16
#define NTHR 128
// cutoff: op*exp(a*d^2) <= e^-14 ~ 8.3e-7; validated rel_err ~9.3e-7 (R7-R16)
#define CULL_LN (-14.0f)
#define NWORD (Nc / 32)        // 2048 bitmap words per (b,tile)

// Scratch (static __device__ arrays — no allocation at runtime)
__device__ float4 g_params[Bc * Nc];            // proj_x, proj_y, a=-0.5/var, op
__device__ float4 g_colop[Nc];                  // (op*cr, op*cg, op*cb, op)
__device__ unsigned int g_bits[Bc * NTILE * NWORD]; // coverage bitmap (1 MB)
__device__ float  g_part[Bc * Gsplit * 4 * HWc];// split-K partials (r,g,b,den)
__device__ int    g_done[Bc * NTILE];           // arrival counters per (b,tile)

// ---------------------------------------------------------------------------
// Kernel 0: zero the coverage bitmap + arrival counters.
// ---------------------------------------------------------------------------
__global__ void k_zero() {
    int i = blockIdx.x * blockDim.x + threadIdx.x;
    g_bits[i] = 0u;                       // grid sized exactly
    if (i < Bc * NTILE) g_done[i] = 0;
}

// ---------------------------------------------------------------------------
// Kernel 1: projection params + colop fold + coverage bitmap (warp-aggregated
//   atomicOr — OR is order-independent => deterministic).
// ---------------------------------------------------------------------------
__global__ void __launch_bounds__(256) k_params(
        const float* __restrict__ pos,
        const float* __restrict__ colors,
        const float* __restrict__ opa,
        const float* __restrict__ scl,
        const float* __restrict__ qv,
        const float* __restrict__ tv,
        const float* __restrict__ fx_,
        const float* __restrict__ fy_,
        const float* __restrict__ cx_,
        const float* __restrict__ cy_) {
    int idx = blockIdx.x * blockDim.x + threadIdx.x;
    if (idx >= Bc * Nc) return;
    int b = idx >> 16;            // Nc = 65536
    int n = idx & (Nc - 1);
    const int lane = threadIdx.x & 31;

    float qw = qv[b * 4 + 0], qx = qv[b * 4 + 1], qy = qv[b * 4 + 2], qz = qv[b * 4 + 3];
    float inv = rsqrtf(qw * qw + qx * qx + qy * qy + qz * qz);
    qw *= inv; qx *= inv; qy *= inv; qz *= inv;

    float R00 = 1.f - 2.f * (qy * qy + qz * qz);
    float R01 = 2.f * (qx * qy - qz * qw);
    float R02 = 2.f * (qx * qz + qy * qw);
    float R10 = 2.f * (qx * qy + qz * qw);
    float R11 = 1.f - 2.f * (qx * qx + qz * qz);
    float R12 = 2.f * (qy * qz - qx * qw);
    float R20 = 2.f * (qx * qz - qy * qw);
    float R21 = 2.f * (qy * qz + qx * qw);
    float R22 = 1.f - 2.f * (qx * qx + qy * qy);

    float px = pos[3 * n], py = pos[3 * n + 1], pz = pos[3 * n + 2];
    float cxm = R00 * px + R01 * py + R02 * pz + tv[b * 3 + 0];
    float cym = R10 * px + R11 * py + R12 * pz + tv[b * 3 + 1];
    float czm = R20 * px + R21 * py + R22 * pz + tv[b * 3 + 2];

    float projx = cxm / czm * fx_[0] + cx_[0];
    float projy = cym / czm * fy_[0] + cy_[0];
    float op = opa[n];
    float s = scl[n];
    float a = -0.5f / (s * s);

    g_params[idx] = make_float4(projx, projy, a, op);
    if (b == 0) {
        g_colop[n] = make_float4(op * colors[3 * n], op * colors[3 * n + 1],
                                 op * colors[3 * n + 2], op);
    }

    // 64-bit tile cover mask (exact clamped-corner test; NaN-safe)
    unsigned long long mask = 0ull;
    float r = sqrtf(CULL_LN / a);              // sqrt(28*var)
    int txlo = (int)fmaxf(0.f, fminf(7.f, floorf((projx - r) * 0.0625f)));
    int txhi = (int)fmaxf(0.f, fminf(7.f, floorf((projx + r) * 0.0625f)));
    int tylo = (int)fmaxf(0.f, fminf(7.f, floorf((projy - r) * 0.0625f)));
    int tyhi = (int)fmaxf(0.f, fminf(7.f, floorf((projy + r) * 0.0625f)));
    for (int ty = tylo; ty <= tyhi; ty++) {
        float ylo = (float)(ty * 16), yhi = ylo + 15.f;
        float ey = fmaxf(fmaxf(ylo - projy, projy - yhi), 0.f);
        for (int tx = txlo; tx <= txhi; tx++) {
            float xlo = (float)(tx * 16), xhi = xlo + 15.f;
            float ex = fmaxf(fmaxf(xlo - projx, projx - xhi), 0.f);
            if (a * (ex * ex + ey * ey) >= CULL_LN)
                mask |= 1ull << (ty * 8 + tx);
        }
    }

    // warp-aggregated bitmap update: one atomicOr per (warp, covered tile)
    unsigned long long uni = mask;
#pragma unroll
    for (int o = 16; o > 0; o >>= 1)
        uni |= __shfl_xor_sync(0xffffffffu, uni, o);
    const int word = n >> 5;                  // warp-uniform (n 32-aligned/warp)
    while (uni) {
        int tl = __ffsll((long long)uni) - 1;
        uni &= uni - 1;
        unsigned bal = __ballot_sync(0xffffffffu, (mask >> tl) & 1ull);
        if (lane == 0)
            atomicOr(&g_bits[((b * NTILE + tl) << 11) + word], bal);
    }
}

// ---------------------------------------------------------------------------
// Kernel 2: culled separable splat, 16x16 tiles, 128-thread blocks.
//   grid = (32 splits, 64 tiles, 2 cams) = 4096 blocks.
//   Phase A: read 64 bitmap words (256 B), popc + shfl-scan, extract bits
//            to the smem list (index-ascending => deterministic order).
//   Phase B: merged staging + inner 8 FFMA + LDS.64 + LDS.128 per gaussian.
//   Tail:    last block per (b,tile) reduces 32 partials in fixed order.
// ---------------------------------------------------------------------------
__global__ void __launch_bounds__(NTHR) k_splat(float* __restrict__ out) {
    __shared__ float  us[KC][TDIMX];        // 2 KB
    __shared__ float4 ds[KC][TDIMY];        // 8 KB
    __shared__ unsigned short list[KN];     // 4 KB
    __shared__ int warptot[2];
    __shared__ int s_last;

    const int t    = threadIdx.x;
    const int g    = blockIdx.x;            // k-split index
    const int tile = blockIdx.y;            // 0..63
    const int b    = blockIdx.z;            // camera
    const int x0   = (tile & (NTX - 1)) * TDIMX;
    const int y0   = (tile / NTX) * TDIMY;
    const int kbase0 = g * KN;
    const int wid  = t >> 5, lane = t & 31;

    const float4* __restrict__ prm = &g_params[b * Nc];

    // ---------------- Phase A: bitmap -> compacted list --------------------
    const unsigned* __restrict__ bits =
        &g_bits[((b * NTILE + tile) << 11) + g * (KN / 32)];
    unsigned w = 0; int c0 = 0;
    if (t < KN / 32) { w = bits[t]; c0 = __popc(w); }
    int incl = c0;
#pragma unroll
    for (int o = 1; o < 32; o <<= 1) {
        int v = __shfl_up_sync(0xffffffffu, incl, o);
        if (lane >= o) incl += v;
    }
    if (t < KN / 32 && lane == 31) warptot[wid] = incl;
    __syncthreads();
    if (t < KN / 32) {
        int pre = incl - c0 + (wid == 1 ? warptot[0] : 0);
        unsigned ww = w;
        const int kb32 = t * 32;
        while (ww) {
            int j = __ffs(ww) - 1;
            ww &= ww - 1;
            list[pre++] = (unsigned short)(kb32 + j);
        }
    }
    __syncthreads();
    const int cnt = warptot[0] + warptot[1];

    // ---------------- Phase B: chunked accumulation over the list ----------
    const int tx  = t & 7;                 // px base = x0 + 2*tx
    const int tyy = t >> 3;                // py = y0 + tyy (0..15)
    const int xu  = t & 15, ku0 = t >> 4;  // staging: 4 slots (k = ku0 + 8i)

    float acc[2][4];
#pragma unroll
    for (int xi = 0; xi < 2; xi++)
#pragma unroll
        for (int ch = 0; ch < 4; ch++) acc[xi][ch] = 0.f;

    for (int kb = 0; kb < cnt; kb += KC) {
        __syncthreads();   // previous chunk consumers done

        // ---- merged staging: one lst/prm/colop load + 2 exps per slot
#pragma unroll
        for (int i = 0; i < 4; i++) {
            int k = ku0 + i * 8;
            int kk = kb + k;
            float u = 0.f;
            float4 dval = make_float4(0.f, 0.f, 0.f, 0.f);
            if (kk < cnt) {
                int n = kbase0 + (int)list[kk];
                float4 pr = prm[n];
                float4 co = g_colop[n];
                float dx = (float)(x0 + xu) - pr.x;
                float dy = (float)(y0 + xu) - pr.y;
                u = __expf(pr.z * dx * dx);
                float e = __expf(pr.z * dy * dy);
                dval = make_float4(co.x * e, co.y * e, co.z * e, co.w * e);
            }
            us[k][xu] = u;
            ds[k][xu] = dval;
        }
        __syncthreads();

        // ---- inner: 8 FFMA + LDS.64 + LDS.128 per k per thread
#pragma unroll 16
        for (int k = 0; k < KC; k++) {
            float2 u2 = *reinterpret_cast<const float2*>(&us[k][tx * 2]);
            float4 d  = ds[k][tyy];
            acc[0][0] += u2.x * d.x;
            acc[0][1] += u2.x * d.y;
            acc[0][2] += u2.x * d.z;
            acc[0][3] += u2.x * d.w;
            acc[1][0] += u2.y * d.x;
            acc[1][1] += u2.y * d.y;
            acc[1][2] += u2.y * d.z;
            acc[1][3] += u2.y * d.w;
        }
    }

    // ---- write deterministic split-K partials (4x STG.64 per thread)
    const int base_bg = ((b * Gsplit + g) * 4) * HWc;
    const int pidx = (y0 + tyy) * Wc + x0 + tx * 2;
#pragma unroll
    for (int ch = 0; ch < 4; ch++) {
        float2 o = make_float2(acc[0][ch], acc[1][ch]);
        *reinterpret_cast<float2*>(&g_part[base_bg + ch * HWc + pidx]) = o;
    }

    // ---------------- Tail: last block per (b,tile) reduces ----------------
    __threadfence();
    __syncthreads();
    if (t == 0) {
        int prev = atomicAdd(&g_done[b * NTILE + tile], 1);
        s_last = (prev == Gsplit - 1);
    }
    __syncthreads();
    if (!s_last) return;

    // reduce 32 partials in fixed split order (deterministic values)
    const int ly = (2 * t) >> 4, lx = (2 * t) & 15;
    const int rp = (y0 + ly) * Wc + x0 + lx;
    float2 r  = make_float2(0.f, 0.f);
    float2 gg = make_float2(0.f, 0.f);
    float2 bb = make_float2(0.f, 0.f);
    float2 dd = make_float2(32.0f * 1e-8f, 32.0f * 1e-8f);  // n_chunks*EPS
#pragma unroll 4
    for (int s = 0; s < Gsplit; s++) {
        const float* pb = &g_part[((b * Gsplit + s) * 4) * HWc + rp];
        float2 v0 = *reinterpret_cast<const float2*>(&pb[0]);
        float2 v1 = *reinterpret_cast<const float2*>(&pb[HWc]);
        float2 v2 = *reinterpret_cast<const float2*>(&pb[2 * HWc]);
        float2 v3 = *reinterpret_cast<const float2*>(&pb[3 * HWc]);
        r.x  += v0.x; r.y  += v0.y;
        gg.x += v1.x; gg.y += v1.y;
        bb.x += v2.x; bb.y += v2.y;
        dd.x += v3.x; dd.y += v3.y;
    }
    float iv0 = 1.0f / fmaxf(dd.x, 1e-8f);
    float iv1 = 1.0f / fmaxf(dd.y, 1e-8f);
    *reinterpret_cast<float2*>(&out[(b * 3 + 0) * HWc + rp]) =
        make_float2(r.x * iv0, r.y * iv1);
    *reinterpret_cast<float2*>(&out[(b * 3 + 1) * HWc + rp]) =
        make_float2(gg.x * iv0, gg.y * iv1);
    *reinterpret_cast<float2*>(&out[(b * 3 + 2) * HWc + rp]) =
        make_float2(bb.x * iv0, bb.y * iv1);
}

// ---------------------------------------------------------------------------
extern "C" void kernel_launch(void* const* d_in, const int* in_sizes, int n_in,
                              void* d_out, int out_size) {
    const float* pos = (const float*)d_in[0];
    const float* col = (const float*)d_in[1];
    const float* opa = (const float*)d_in[2];
    const float* scl = (const float*)d_in[3];
    const float* qv  = (const float*)d_in[4];
    const float* tv  = (const float*)d_in[5];
    const float* fx  = (const float*)d_in[6];
    const float* fy  = (const float*)d_in[7];
    const float* cx  = (const float*)d_in[8];
    const float* cy  = (const float*)d_in[9];

    k_zero<<<(Bc * NTILE * NWORD) / 256, 256>>>();
    k_params<<<(Bc * Nc) / 256, 256>>>(pos, col, opa, scl, qv, tv, fx, fy, cx, cy);

    dim3 grid(Gsplit, NTILE, Bc);   // 32 * 64 * 2 = 4096 blocks
    k_splat<<<grid, NTHR>>>((float*)d_out);
}